// round 3
// baseline (speedup 1.0000x reference)
#include <cuda_runtime.h>

#define LDIM 24
#define VOL (LDIM*LDIM*LDIM*LDIM)   /* 331776 */
#define NELEM (4*VOL*9)             /* 11943936 */

struct Mat { float re[9]; float im[9]; };

__device__ __forceinline__ int wrapp(int c){ return (c==LDIM-1) ? 0 : c+1; }
__device__ __forceinline__ int wrapm(int c){ return (c==0) ? (LDIM-1) : c-1; }

__device__ __forceinline__ int baseidx(int dir,int t,int z,int y,int x){
  return ((((dir*LDIM + t)*LDIM + z)*LDIM + y)*LDIM + x)*9;
}

// Load a 3x3 complex matrix from the interleaved (re,im) buffer: 9 x float2.
__device__ __forceinline__ void loadM(Mat& M, const float2* __restrict__ u, int b){
#pragma unroll
  for(int j=0;j<9;j++){
    float2 v = __ldg(u + b + j);
    M.re[j] = v.x; M.im[j] = v.y;
  }
}

// C = A @ B
__device__ __forceinline__ void mm(Mat& C, const Mat& A, const Mat& B){
#pragma unroll
  for(int a=0;a<3;a++){
#pragma unroll
    for(int b=0;b<3;b++){
      float cr=0.f, ci=0.f;
#pragma unroll
      for(int k=0;k<3;k++){
        float ar=A.re[a*3+k], ai=A.im[a*3+k];
        float br=B.re[k*3+b], bi=B.im[k*3+b];
        cr = fmaf(ar,br,cr); cr = fmaf(-ai,bi,cr);
        ci = fmaf(ar,bi,ci); ci = fmaf( ai,br,ci);
      }
      C.re[a*3+b]=cr; C.im[a*3+b]=ci;
    }
  }
}

// C = A @ B^dag
__device__ __forceinline__ void mm_nd(Mat& C, const Mat& A, const Mat& B){
#pragma unroll
  for(int a=0;a<3;a++){
#pragma unroll
    for(int b=0;b<3;b++){
      float cr=0.f, ci=0.f;
#pragma unroll
      for(int k=0;k<3;k++){
        float ar=A.re[a*3+k], ai=A.im[a*3+k];
        float br=B.re[b*3+k], bi=-B.im[b*3+k];
        cr = fmaf(ar,br,cr); cr = fmaf(-ai,bi,cr);
        ci = fmaf(ar,bi,ci); ci = fmaf( ai,br,ci);
      }
      C.re[a*3+b]=cr; C.im[a*3+b]=ci;
    }
  }
}

// C = A^dag @ B
__device__ __forceinline__ void mm_dn(Mat& C, const Mat& A, const Mat& B){
#pragma unroll
  for(int a=0;a<3;a++){
#pragma unroll
    for(int b=0;b<3;b++){
      float cr=0.f, ci=0.f;
#pragma unroll
      for(int k=0;k<3;k++){
        float ar=A.re[k*3+a], ai=-A.im[k*3+a];
        float br=B.re[k*3+b], bi=B.im[k*3+b];
        cr = fmaf(ar,br,cr); cr = fmaf(-ai,bi,cr);
        ci = fmaf(ar,bi,ci); ci = fmaf( ai,br,ci);
      }
      C.re[a*3+b]=cr; C.im[a*3+b]=ci;
    }
  }
}

__device__ __forceinline__ void axpy(Mat& F, float c, const Mat& T){
#pragma unroll
  for(int j=0;j<9;j++){ F.re[j] = fmaf(c, T.re[j], F.re[j]); F.im[j] = fmaf(c, T.im[j], F.im[j]); }
}

// Copy kernel: interleave (re, im) -> output [..., 2], vectorized float4.
__global__ void __launch_bounds__(256) copy_kernel(const float4* __restrict__ re,
                                                   const float4* __restrict__ im,
                                                   float4* __restrict__ out, int n4){
  int i = blockIdx.x*blockDim.x + threadIdx.x;
  if (i >= n4) return;
  float4 r = re[i];
  float4 m = im[i];
  out[2*i + 0] = make_float4(r.x, m.x, r.y, m.y);
  out[2*i + 1] = make_float4(r.z, m.z, r.w, m.w);
}

// Stout update on direction-0 even sites. Reads from the freshly-written
// interleaved output buffer (float2 loads, partially L2-resident); writes
// only dir-0 even-site matrices, which no other thread reads.
__global__ void __launch_bounds__(256) stout_kernel(const float* __restrict__ coeff,
                                                    float2* __restrict__ out){
  const int NEVEN = VOL/2;  // 165888
  int tid = blockIdx.x*blockDim.x + threadIdx.x;
  if (tid >= NEVEN) return;
  const float2* __restrict__ u = out;

  int k = tid % (LDIM/2);
  int r = tid / (LDIM/2);
  int y = r % LDIM; r /= LDIM;
  int z = r % LDIM; r /= LDIM;
  int t = r;
  int x = 2*k + ((t + z + y) & 1);   // even parity: (t+z+y+x)%2 == 0

  // scale_coeff: (2/pi)*0.75*atan(c)
  float cc[6];
#pragma unroll
  for(int i=0;i<6;i++) cc[i] = 0.47746982f * atanf(__ldg(coeff+i));

  const int tp = wrapp(t);

  Mat f;
#pragma unroll
  for(int j=0;j<9;j++){ f.re[j]=0.f; f.im[j]=0.f; }

  Mat A, B, T1, T2;
#pragma unroll
  for(int nu=1; nu<4; nu++){
    int cp[4] = {t,z,y,x};
    int cm[4] = {t,z,y,x};
    cp[nu] = wrapp(cp[nu]);
    cm[nu] = wrapm(cm[nu]);

    int b_x0_sp    = baseidx(0 , cp[0],cp[1],cp[2],cp[3]);  // x[0](s+nu)   (odd site)
    int b_xnu_smu  = baseidx(nu, tp, z, y, x);              // x[nu](s+t)
    int b_xnu_s    = baseidx(nu, t , z, y, x);              // x[nu](s)
    int b_xnu_sm   = baseidx(nu, cm[0],cm[1],cm[2],cm[3]);  // x[nu](s-nu)
    int b_x0_sm    = baseidx(0 , cm[0],cm[1],cm[2],cm[3]);  // x[0](s-nu)   (odd site)
    int b_xnu_smmu = baseidx(nu, tp, cm[1],cm[2],cm[3]);    // x[nu](s-nu+t)

    // forward staple: x[nu](s) @ x[0](s+nu) @ x[nu](s+t)^dag
    loadM(A, u, b_x0_sp);
    loadM(B, u, b_xnu_smu);
    mm_nd(T1, A, B);
    loadM(A, u, b_xnu_s);
    mm(T2, A, T1);
    axpy(f, cc[2*(nu-1)], T2);

    // backward staple: x[nu](s-nu)^dag @ x[0](s-nu) @ x[nu](s-nu+t)
    loadM(A, u, b_xnu_sm);
    loadM(B, u, b_x0_sm);
    mm_dn(T1, A, B);
    loadM(B, u, b_xnu_smmu);
    mm(T2, T1, B);
    axpy(f, cc[2*(nu-1)+1], T2);
  }

  const float inv6 = 1.0f/6.0f;
#pragma unroll
  for(int j=0;j<9;j++){ f.re[j]*=inv6; f.im[j]*=inv6; }

  // U = x[0](s)  (this thread's own site; read before write, no cross-thread hazard)
  Mat U;
  int b0 = baseidx(0, t, z, y, x);
  loadM(U, u, b0);

  // M = f @ U^dag
  Mat M;
  mm_nd(M, f, U);

  // Z = 0.5*(M - M^dag) - trace/3 * I, then scale by 0.5^4
  Mat Z;
#pragma unroll
  for(int a=0;a<3;a++){
#pragma unroll
    for(int b=0;b<3;b++){
      Z.re[a*3+b] = 0.5f*(M.re[a*3+b] - M.re[b*3+a]);
      Z.im[a*3+b] = 0.5f*(M.im[a*3+b] + M.im[b*3+a]);
    }
  }
  float trr = (Z.re[0]+Z.re[4]+Z.re[8]) * (1.0f/3.0f);
  float tri = (Z.im[0]+Z.im[4]+Z.im[8]) * (1.0f/3.0f);
  Z.re[0]-=trr; Z.re[4]-=trr; Z.re[8]-=trr;
  Z.im[0]-=tri; Z.im[4]-=tri; Z.im[8]-=tri;
#pragma unroll
  for(int j=0;j<9;j++){ Z.re[j]*=0.0625f; Z.im[j]*=0.0625f; }

  // Horner Taylor: E = I; for k=12..1: E = I + (Z@E)/k
  // Ping-pong between E0/E1 to avoid an explicit copy loop after each mm.
  Mat E0, E1;
#pragma unroll
  for(int j=0;j<9;j++){
    E0.re[j] = (j==0||j==4||j==8) ? 1.f : 0.f;
    E0.im[j] = 0.f;
  }
#pragma unroll
  for(int kk=12; kk>=1; kk--){
    mm(E1, Z, E0);
    float invk = 1.0f/(float)kk;
#pragma unroll
    for(int j=0;j<9;j++){
      E0.re[j] = E1.re[j]*invk + ((j==0||j==4||j==8) ? 1.f : 0.f);
      E0.im[j] = E1.im[j]*invk;
    }
  }
  // 4 squarings: E0 -> E1 -> E0 -> E1 -> E0
  mm(E1, E0, E0);
  mm(E0, E1, E1);
  mm(E1, E0, E0);
  mm(E0, E1, E1);

  // Y = E0 @ U  -> write to out (dir 0, site s)
  mm(E1, E0, U);
#pragma unroll
  for(int j=0;j<9;j++){
    out[b0 + j] = make_float2(E1.re[j], E1.im[j]);
  }
}

extern "C" void kernel_launch(void* const* d_in, const int* in_sizes, int n_in,
                              void* d_out, int out_size) {
  const float* xre   = (const float*)d_in[0];
  const float* xim   = (const float*)d_in[1];
  const float* coeff = (const float*)d_in[2];
  float* out = (float*)d_out;

  // 1) copy/interleave everything (dirs 1-3, and odd sites of dir 0 are passthrough)
  int n4 = NELEM/4;  // 2985984
  copy_kernel<<<(n4+255)/256, 256>>>((const float4*)xre, (const float4*)xim,
                                     (float4*)out, n4);

  // 2) stout update overwrites dir-0 even sites, reading the interleaved buffer
  int neven = VOL/2;
  stout_kernel<<<(neven+255)/256, 256>>>(coeff, (float2*)out);
}

// round 14
// speedup vs baseline: 1.0297x; 1.0297x over previous
#include <cuda_runtime.h>

#define LDIM 24
#define VOL (LDIM*LDIM*LDIM*LDIM)   /* 331776 */
#define NEVEN (VOL/2)               /* 165888 */
#define NELEM (4*VOL*9)             /* 11943936 */

struct Mat { float re[9]; float im[9]; };

__device__ __forceinline__ int wrapp(int c){ return (c==LDIM-1) ? 0 : c+1; }
__device__ __forceinline__ int wrapm(int c){ return (c==0) ? (LDIM-1) : c-1; }

__device__ __forceinline__ int baseidx(int dir,int t,int z,int y,int x){
  return ((((dir*LDIM + t)*LDIM + z)*LDIM + y)*LDIM + x)*9;
}

// Load a 3x3 complex matrix from the interleaved buffer: 9 x float2.
__device__ __forceinline__ void loadM2(Mat& M, const float2* __restrict__ u, int b){
#pragma unroll
  for(int j=0;j<9;j++){
    float2 v = __ldg(u + b + j);
    M.re[j] = v.x; M.im[j] = v.y;
  }
}

// Load a 3x3 complex matrix from split re/im input arrays.
__device__ __forceinline__ void loadMS(Mat& M, const float* __restrict__ re,
                                       const float* __restrict__ im, int b){
#pragma unroll
  for(int j=0;j<9;j++){ M.re[j]=__ldg(re+b+j); M.im[j]=__ldg(im+b+j); }
}

// C = A @ B
__device__ __forceinline__ void mm(Mat& C, const Mat& A, const Mat& B){
#pragma unroll
  for(int a=0;a<3;a++){
#pragma unroll
    for(int b=0;b<3;b++){
      float cr=0.f, ci=0.f;
#pragma unroll
      for(int k=0;k<3;k++){
        float ar=A.re[a*3+k], ai=A.im[a*3+k];
        float br=B.re[k*3+b], bi=B.im[k*3+b];
        cr = fmaf(ar,br,cr); cr = fmaf(-ai,bi,cr);
        ci = fmaf(ar,bi,ci); ci = fmaf( ai,br,ci);
      }
      C.re[a*3+b]=cr; C.im[a*3+b]=ci;
    }
  }
}

// C = A @ B^dag
__device__ __forceinline__ void mm_nd(Mat& C, const Mat& A, const Mat& B){
#pragma unroll
  for(int a=0;a<3;a++){
#pragma unroll
    for(int b=0;b<3;b++){
      float cr=0.f, ci=0.f;
#pragma unroll
      for(int k=0;k<3;k++){
        float ar=A.re[a*3+k], ai=A.im[a*3+k];
        float br=B.re[b*3+k], bi=-B.im[b*3+k];
        cr = fmaf(ar,br,cr); cr = fmaf(-ai,bi,cr);
        ci = fmaf(ar,bi,ci); ci = fmaf( ai,br,ci);
      }
      C.re[a*3+b]=cr; C.im[a*3+b]=ci;
    }
  }
}

// C = A^dag @ B
__device__ __forceinline__ void mm_dn(Mat& C, const Mat& A, const Mat& B){
#pragma unroll
  for(int a=0;a<3;a++){
#pragma unroll
    for(int b=0;b<3;b++){
      float cr=0.f, ci=0.f;
#pragma unroll
      for(int k=0;k<3;k++){
        float ar=A.re[k*3+a], ai=-A.im[k*3+a];
        float br=B.re[k*3+b], bi=B.im[k*3+b];
        cr = fmaf(ar,br,cr); cr = fmaf(-ai,bi,cr);
        ci = fmaf(ar,bi,ci); ci = fmaf( ai,br,ci);
      }
      C.re[a*3+b]=cr; C.im[a*3+b]=ci;
    }
  }
}

__device__ __forceinline__ void axpy(Mat& F, float c, const Mat& T){
#pragma unroll
  for(int j=0;j<9;j++){ F.re[j] = fmaf(c, T.re[j], F.re[j]); F.im[j] = fmaf(c, T.im[j], F.im[j]); }
}

// Copy kernel: interleave (re, im) -> output [..., 2] for dirs 1..3 only.
// Pointers are pre-offset to the start of dir 1.
__global__ void __launch_bounds__(256) copy_kernel(const float4* __restrict__ re,
                                                   const float4* __restrict__ im,
                                                   float4* __restrict__ out, int n4){
  int i = blockIdx.x*blockDim.x + threadIdx.x;
  if (i >= n4) return;
  float4 r = re[i];
  float4 m = im[i];
  out[2*i + 0] = make_float4(r.x, m.x, r.y, m.y);
  out[2*i + 1] = make_float4(r.z, m.z, r.w, m.w);
}

// Direction-0 kernel, parity-pure warps:
//   tid in [0, NEVEN)    : stout update on even site  (heavy)
//   tid in [NEVEN, VOL)  : passthrough copy of odd site (cheap; fills latency)
// Stout reads dirs 1-3 from `out` (written by copy_kernel, float2 loads) and
// dir-0 matrices from the raw inputs (odd-copy warps write, never read, so no hazard).
// __launch_bounds__(128, 5): cap regs at 102 so 5 blocks (20 warps) fit per SM.
__global__ void __launch_bounds__(128, 5) dir0_kernel(const float* __restrict__ xre,
                                                      const float* __restrict__ xim,
                                                      const float* __restrict__ coeff,
                                                      float2* __restrict__ out){
  int tid = blockIdx.x*blockDim.x + threadIdx.x;
  if (tid >= VOL) return;

  if (tid >= NEVEN) {
    // ---- odd-site dir-0 passthrough ----
    int s = tid - NEVEN;
    int k = s % (LDIM/2);
    int r = s / (LDIM/2);
    int y = r % LDIM; r /= LDIM;
    int z = r % LDIM; r /= LDIM;
    int t = r;
    int x = 2*k + (((t + z + y) & 1) ^ 1);  // odd parity
    int b0 = baseidx(0, t, z, y, x);
#pragma unroll
    for(int j=0;j<9;j++){
      out[b0 + j] = make_float2(__ldg(xre + b0 + j), __ldg(xim + b0 + j));
    }
    return;
  }

  // ---- even-site stout update ----
  const float2* __restrict__ u = out;

  int k = tid % (LDIM/2);
  int r = tid / (LDIM/2);
  int y = r % LDIM; r /= LDIM;
  int z = r % LDIM; r /= LDIM;
  int t = r;
  int x = 2*k + ((t + z + y) & 1);   // even parity: (t+z+y+x)%2 == 0

  // scale_coeff: (2/pi)*0.75*atan(c)
  float cc[6];
#pragma unroll
  for(int i=0;i<6;i++) cc[i] = 0.47746982f * atanf(__ldg(coeff+i));

  const int tp = wrapp(t);

  Mat f;
#pragma unroll
  for(int j=0;j<9;j++){ f.re[j]=0.f; f.im[j]=0.f; }

  Mat A, B, T1, T2;
#pragma unroll
  for(int nu=1; nu<4; nu++){
    int cp[4] = {t,z,y,x};
    int cm[4] = {t,z,y,x};
    cp[nu] = wrapp(cp[nu]);
    cm[nu] = wrapm(cm[nu]);

    int b_x0_sp    = baseidx(0 , cp[0],cp[1],cp[2],cp[3]);  // x[0](s+nu)   odd site, from inputs
    int b_xnu_smu  = baseidx(nu, tp, z, y, x);              // x[nu](s+t)   from out
    int b_xnu_s    = baseidx(nu, t , z, y, x);              // x[nu](s)     from out
    int b_xnu_sm   = baseidx(nu, cm[0],cm[1],cm[2],cm[3]);  // x[nu](s-nu)  from out
    int b_x0_sm    = baseidx(0 , cm[0],cm[1],cm[2],cm[3]);  // x[0](s-nu)   odd site, from inputs
    int b_xnu_smmu = baseidx(nu, tp, cm[1],cm[2],cm[3]);    // x[nu](s-nu+t) from out

    // forward staple: x[nu](s) @ x[0](s+nu) @ x[nu](s+t)^dag
    loadMS(A, xre, xim, b_x0_sp);
    loadM2(B, u, b_xnu_smu);
    mm_nd(T1, A, B);
    loadM2(A, u, b_xnu_s);
    mm(T2, A, T1);
    axpy(f, cc[2*(nu-1)], T2);

    // backward staple: x[nu](s-nu)^dag @ x[0](s-nu) @ x[nu](s-nu+t)
    loadM2(A, u, b_xnu_sm);
    loadMS(B, xre, xim, b_x0_sm);
    mm_dn(T1, A, B);
    loadM2(B, u, b_xnu_smmu);
    mm(T2, T1, B);
    axpy(f, cc[2*(nu-1)+1], T2);
  }

  const float inv6 = 1.0f/6.0f;
#pragma unroll
  for(int j=0;j<9;j++){ f.re[j]*=inv6; f.im[j]*=inv6; }

  // U = x[0](s) from inputs (this thread's own site)
  Mat U;
  int b0 = baseidx(0, t, z, y, x);
  loadMS(U, xre, xim, b0);

  // M = f @ U^dag
  Mat M;
  mm_nd(M, f, U);

  // Z = 0.5*(M - M^dag) - trace/3 * I, then scale by 0.5^4
  Mat Z;
#pragma unroll
  for(int a=0;a<3;a++){
#pragma unroll
    for(int b=0;b<3;b++){
      Z.re[a*3+b] = 0.5f*(M.re[a*3+b] - M.re[b*3+a]);
      Z.im[a*3+b] = 0.5f*(M.im[a*3+b] + M.im[b*3+a]);
    }
  }
  float trr = (Z.re[0]+Z.re[4]+Z.re[8]) * (1.0f/3.0f);
  float tri = (Z.im[0]+Z.im[4]+Z.im[8]) * (1.0f/3.0f);
  Z.re[0]-=trr; Z.re[4]-=trr; Z.re[8]-=trr;
  Z.im[0]-=tri; Z.im[4]-=tri; Z.im[8]-=tri;
#pragma unroll
  for(int j=0;j<9;j++){ Z.re[j]*=0.0625f; Z.im[j]*=0.0625f; }

  // Horner Taylor: E = I; for k=12..1: E = I + (Z@E)/k   (ping-pong E0/E1)
  Mat E0, E1;
#pragma unroll
  for(int j=0;j<9;j++){
    E0.re[j] = (j==0||j==4||j==8) ? 1.f : 0.f;
    E0.im[j] = 0.f;
  }
#pragma unroll
  for(int kk=12; kk>=1; kk--){
    mm(E1, Z, E0);
    float invk = 1.0f/(float)kk;
#pragma unroll
    for(int j=0;j<9;j++){
      E0.re[j] = E1.re[j]*invk + ((j==0||j==4||j==8) ? 1.f : 0.f);
      E0.im[j] = E1.im[j]*invk;
    }
  }
  // 4 squarings
  mm(E1, E0, E0);
  mm(E0, E1, E1);
  mm(E1, E0, E0);
  mm(E0, E1, E1);

  // Y = E0 @ U  -> write to out (dir 0, site s)
  mm(E1, E0, U);
#pragma unroll
  for(int j=0;j<9;j++){
    out[b0 + j] = make_float2(E1.re[j], E1.im[j]);
  }
}

extern "C" void kernel_launch(void* const* d_in, const int* in_sizes, int n_in,
                              void* d_out, int out_size) {
  const float* xre   = (const float*)d_in[0];
  const float* xim   = (const float*)d_in[1];
  const float* coeff = (const float*)d_in[2];
  float* out = (float*)d_out;

  // 1) copy/interleave dirs 1..3 (contiguous region starting at VOL*9 floats)
  const int dir1_off = VOL*9;          // float offset of dir 1
  int n4 = (3*VOL*9)/4;                // 2239488 float4s
  copy_kernel<<<(n4+255)/256, 256>>>((const float4*)(xre + dir1_off),
                                     (const float4*)(xim + dir1_off),
                                     (float4*)(out + 2*dir1_off), n4);

  // 2) dir-0: stout on even sites + passthrough on odd sites
  int nthreads = VOL;
  dir0_kernel<<<(nthreads+127)/128, 128>>>(xre, xim, coeff, (float2*)out);
}